// round 16
// baseline (speedup 1.0000x reference)
#include <cuda_runtime.h>
#include <cuda_fp16.h>
#include <math.h>
#include <stdint.h>
typedef __half h16;

#define DD    2560
#define HDIM  320
#define NH    8
#define SEGL  1024
#define STOT  4096
#define BATCH 2
#define MMEM  128
#define NSEG  4
#define MBIG  (BATCH*SEGL)
#define MSM   (BATCH*MMEM)
#define BKT   32
#define KCH   32
#define KP    322   // K/V smem row pitch (h16): bank stride 161 = conflict-free

// fp32 scratch
__device__ float g_gate[MBIG*DD], g_nm[MSM*DD];
__device__ float g_memA[MSM*DD], g_memB[MSM*DD];
// fp16 scratch
#define WMAT (DD*DD)
__device__ __align__(16) h16 g_whi[11LL*WMAT];
__device__ __align__(16) h16 g_hidhi[BATCH*STOT*DD];
__device__ __align__(16) h16 g_qrh[MBIG*DD], g_kwh[MBIG*DD], g_vwh[MBIG*DD];
__device__ __align__(16) h16 g_krh[MSM*DD], g_vrh[MSM*DD], g_qwh[MSM*DD];
__device__ __align__(16) h16 g_chi[MBIG*DD];
__device__ __align__(16) h16 g_ahi[MBIG*DD];
__device__ __align__(16) h16 g_awhi[MSM*DD];
__device__ __align__(16) h16 g_cathi[MSM*2*DD];
__device__ __align__(16) h16 g_mAhi[MSM*DD];
__device__ __align__(16) h16 g_mBhi[MSM*DD];
__device__ __align__(16) h16 g_imhi[MMEM*DD];
__device__ __align__(16) h16 g_wqhi[MMEM*DD];

#define OW_QR (0LL*WMAT)
#define OW_KR (1LL*WMAT)
#define OW_VR (2LL*WMAT)
#define OW_OR (3LL*WMAT)
#define OW_GR (4LL*WMAT)
#define OW_QW (5LL*WMAT)
#define OW_KW (6LL*WMAT)
#define OW_VW (7LL*WMAT)
#define OW_OW (8LL*WMAT)
#define OW_GW (9LL*WMAT)

__device__ __forceinline__ void cp16(uint32_t s, const void* g) {
    asm volatile("cp.async.cg.shared.global [%0], [%1], 16;\n" :: "r"(s), "l"(g));
}
__device__ __forceinline__ void ldsm4(uint32_t& r0, uint32_t& r1, uint32_t& r2,
                                      uint32_t& r3, uint32_t a) {
    asm volatile("ldmatrix.sync.aligned.m8n8.x4.shared.b16 {%0,%1,%2,%3}, [%4];"
                 : "=r"(r0), "=r"(r1), "=r"(r2), "=r"(r3) : "r"(a));
}
__device__ __forceinline__ void ldsm4t(uint32_t& r0, uint32_t& r1, uint32_t& r2,
                                       uint32_t& r3, uint32_t a) {
    asm volatile("ldmatrix.sync.aligned.m8n8.x4.trans.shared.b16 {%0,%1,%2,%3}, [%4];"
                 : "=r"(r0), "=r"(r1), "=r"(r2), "=r"(r3) : "r"(a));
}
__device__ __forceinline__ void mma16816(float* c, const uint32_t* a, const uint32_t* b) {
    asm volatile("mma.sync.aligned.m16n8k16.row.col.f32.f16.f16.f32 "
                 "{%0,%1,%2,%3}, {%4,%5,%6,%7}, {%8,%9}, {%0,%1,%2,%3};"
                 : "+f"(c[0]), "+f"(c[1]), "+f"(c[2]), "+f"(c[3])
                 : "r"(a[0]), "r"(a[1]), "r"(a[2]), "r"(a[3]), "r"(b[0]), "r"(b[1]));
}
__device__ __forceinline__ float sig_(float x) { return 1.0f / (1.0f + __expf(-x)); }

// ---- single-pass fp16 HMMA GEMM, 3-stage cp.async pipeline ------------------
// OUT 0: C fp32 only.  OUT 1: C fp32 + Shi h16.  OUT 2: Shi h16 only.
template<int BM, int BN_, int MT, int NT_, int EPI, int OUT>
__global__ void __launch_bounds__(256, 2)
mma_gemm(const h16* __restrict__ Ah, const h16* __restrict__ Wh,
         float* __restrict__ C, h16* __restrict__ Shi,
         int N, int K, int a_cr, long long a_cs, int c_cr, long long c_cs,
         const float* __restrict__ aux0, const float* __restrict__ aux1,
         const float* __restrict__ aux2) {
    constexpr int WM = MT * 16, WN = NT_ * 8;
    constexpr int A_ROWB = BKT * 2 + 16;
    constexpr int B_ROWB = BN_ * 2 + 16;
    constexpr int A_TILE = BM * A_ROWB;
    constexpr int B_TILE = BKT * B_ROWB;
    constexpr int STAGE = A_TILE + B_TILE;
    constexpr int BCH = BN_ / 8;

    extern __shared__ char smem_raw[];
    const uint32_t sbase = (uint32_t)__cvta_generic_to_shared(smem_raw);

    const int tid = threadIdx.x;
    const int m0 = blockIdx.y * BM, n0 = blockIdx.x * BN_;
    const int warp = tid >> 5, lane = tid & 31;
    const int wid_m = warp >> 1, wid_n = warp & 1;
    const long long arow0 = (long long)(m0 / a_cr) * a_cs + (m0 % a_cr);

    float acc[MT][NT_][4];
#pragma unroll
    for (int i = 0; i < MT; ++i)
#pragma unroll
        for (int j = 0; j < NT_; ++j)
#pragma unroll
            for (int e = 0; e < 4; ++e) acc[i][j][e] = 0.0f;

    const int NKI = K / BKT;

    auto ldst = [&](int ks, int st) {
        const int k0 = ks * BKT;
        const uint32_t sb = sbase + st * STAGE;
#pragma unroll
        for (int t = 0; t < (BM * 4) / 256; ++t) {
            const int c = tid + t * 256;
            const int r = c >> 2, kc = (c & 3) * 8;
            const uint32_t off = r * A_ROWB + kc * 2;
            const long long gi = (arow0 + r) * (long long)K + k0 + kc;
            cp16(sb + off, Ah + gi);
        }
        for (int c = tid; c < 4 * BN_; c += 256) {
            const int r = c / BCH, nc = c % BCH;
            const uint32_t off = A_TILE + r * B_ROWB + nc * 16;
            const long long gi = (long long)(k0 + r) * N + n0 + nc * 8;
            cp16(sb + off, Wh + gi);
        }
        asm volatile("cp.async.commit_group;\n");
    };

    ldst(0, 0); ldst(1, 1); ldst(2, 2);

    for (int ks = 0; ks < NKI; ++ks) {
        if      (ks < NKI - 2) asm volatile("cp.async.wait_group 2;\n");
        else if (ks < NKI - 1) asm volatile("cp.async.wait_group 1;\n");
        else                   asm volatile("cp.async.wait_group 0;\n");
        __syncthreads();
        const uint32_t sb = sbase + (ks % 3) * STAGE;

#pragma unroll
        for (int kk = 0; kk < BKT; kk += 16) {
            uint32_t ah[MT][4], b[NT_][2];
            const int arow = wid_m * WM + (lane & 15);
            const int acol = kk + (lane >> 4) * 8;
#pragma unroll
            for (int i = 0; i < MT; ++i) {
                const uint32_t ad = sb + (arow + i * 16) * A_ROWB + acol * 2;
                ldsm4(ah[i][0], ah[i][1], ah[i][2], ah[i][3], ad);
            }
            const int brow = kk + (lane & 15);
            const uint32_t bbase = sb + A_TILE + brow * B_ROWB;
#pragma unroll
            for (int j2 = 0; j2 < NT_ / 2; ++j2) {
                const int bcol = wid_n * WN + j2 * 16 + (lane >> 4) * 8;
                ldsm4t(b[2*j2][0], b[2*j2][1], b[2*j2+1][0], b[2*j2+1][1],
                       bbase + bcol * 2);
            }
#pragma unroll
            for (int i = 0; i < MT; ++i)
#pragma unroll
                for (int j = 0; j < NT_; ++j)
                    mma16816(acc[i][j], ah[i], b[j]);
        }
        __syncthreads();
        if (ks + 3 < NKI) ldst(ks + 3, (ks + 3) % 3);
    }

    const int gid = lane >> 2, tig = lane & 3;
    const long long crow0 = (long long)(m0 / c_cr) * c_cs + (m0 % c_cr);

#pragma unroll
    for (int i = 0; i < MT; ++i) {
        const int r = wid_m * WM + i * 16 + gid;
#pragma unroll
        for (int j = 0; j < NT_; ++j) {
            const int col = n0 + wid_n * WN + j * 8 + 2 * tig;
#pragma unroll
            for (int half = 0; half < 2; ++half) {
                const int rr = r + half * 8;
                const long long ci = (crow0 + rr) * (long long)N + col;
                const long long li = (long long)(m0 + rr) * N + col;
                float2 v;
#pragma unroll
                for (int e = 0; e < 2; ++e) {
                    const float a = acc[i][j][2 * half + e];
                    float o;
                    if      (EPI == 0) o = a;
                    else if (EPI == 1) o = sig_(a + aux0[col + e]);
                    else if (EPI == 2) o = aux1[ci + e] + aux2[li + e] * a;
                    else { const float s = sig_(a + aux0[col + e]);
                           o = s * aux1[li + e] + (1.0f - s) * aux2[li + e]; }
                    (&v.x)[e] = o;
                }
                if (OUT <= 1) *reinterpret_cast<float2*>(C + ci) = v;
                if (OUT >= 1)
                    *reinterpret_cast<__half2*>(Shi + li) =
                        __half2(__float2half_rn(v.x), __float2half_rn(v.y));
            }
        }
    }
}

// ---- shfl-free flash attention: 16 q/block, 32-key fp16 chunks --------------
// warp w owns queries 2w, 2w+1; lane l owns key l of each chunk and dims l+32t.
__global__ void __launch_bounds__(256)
attn16(const h16* __restrict__ Q, const h16* __restrict__ Kp,
       const h16* __restrict__ V, h16* __restrict__ O,
       int Lq, int Lk, float scale) {
    __shared__ h16 Qs[16][HDIM];
    __shared__ float paS[8][2][32];
    extern __shared__ h16 kvs[];
    h16* Ks = kvs;                 // [KCH][KP]
    h16* Vs = kvs + KCH * KP;      // [KCH][KP]

    const int h = blockIdx.y, b = blockIdx.z, q0 = blockIdx.x * 16;
    const int tid = threadIdx.x, w = tid >> 5, l = tid & 31;
    const int qa = 2 * w;

    const h16* Qg = Q + ((long long)(b * Lq + q0)) * DD + h * HDIM;
#pragma unroll
    for (int t = 0; t < 10; ++t) {
        const int idx = tid + t * 256;
        const int row = idx / 160, c2 = idx % 160;
        *reinterpret_cast<uint32_t*>(&Qs[row][c2 * 2]) =
            *reinterpret_cast<const uint32_t*>(Qg + (long long)row * DD + c2 * 2);
    }

    float mrun = -1e30f, sA = 0.0f, sB = 0.0f, accA[10], accB[10];
#pragma unroll
    for (int t = 0; t < 10; ++t) { accA[t] = 0.0f; accB[t] = 0.0f; }

    for (int c = 0; c < Lk / KCH; ++c) {
        const h16* Kg = Kp + ((long long)(b * Lk + c * KCH)) * DD + h * HDIM;
        const h16* Vg = V  + ((long long)(b * Lk + c * KCH)) * DD + h * HDIM;
        __syncthreads();
#pragma unroll
        for (int t = 0; t < 20; ++t) {
            const int idx = tid + t * 256;           // 0..5119
            const int row = idx / 160, c2 = idx % 160;
            *reinterpret_cast<uint32_t*>(&Ks[row * KP + c2 * 2]) =
                *reinterpret_cast<const uint32_t*>(Kg + (long long)row * DD + c2 * 2);
            *reinterpret_cast<uint32_t*>(&Vs[row * KP + c2 * 2]) =
                *reinterpret_cast<const uint32_t*>(Vg + (long long)row * DD + c2 * 2);
        }
        __syncthreads();

        // scores: lane l <-> key l (conflict-free: KP*2/4 = 161 ≡ 1 mod 32)
        float dA = 0.0f, dB = 0.0f;
#pragma unroll 8
        for (int d2 = 0; d2 < 160; ++d2) {
            const float2 kv = __half22float2(
                *reinterpret_cast<const __half2*>(&Ks[l * KP + 2 * d2]));
            const float2 q1 = __half22float2(
                *reinterpret_cast<const __half2*>(&Qs[qa][2 * d2]));
            const float2 q2 = __half22float2(
                *reinterpret_cast<const __half2*>(&Qs[qa + 1][2 * d2]));
            dA += q1.x * kv.x + q1.y * kv.y;
            dB += q2.x * kv.x + q2.y * kv.y;
        }
        dA *= scale; dB *= scale;

        float cm = fmaxf(dA, dB);
#pragma unroll
        for (int o = 16; o > 0; o >>= 1)
            cm = fmaxf(cm, __shfl_xor_sync(0xFFFFFFFF, cm, o));
        const float mn = fmaxf(mrun, cm);
        const float cr = __expf(mrun - mn);
        const float pa = __expf(dA - mn), pb = __expf(dB - mn);
        float psA = pa, psB = pb;
#pragma unroll
        for (int o = 16; o > 0; o >>= 1) {
            psA += __shfl_xor_sync(0xFFFFFFFF, psA, o);
            psB += __shfl_xor_sync(0xFFFFFFFF, psB, o);
        }
        sA = sA * cr + psA;
        sB = sB * cr + psB;
#pragma unroll
        for (int t = 0; t < 10; ++t) { accA[t] *= cr; accB[t] *= cr; }
        mrun = mn;
        paS[w][0][l] = pa;
        paS[w][1][l] = pb;
        __syncwarp();

#pragma unroll 4
        for (int k = 0; k < KCH; ++k) {
            const float fa = paS[w][0][k], fb = paS[w][1][k];
#pragma unroll
            for (int t = 0; t < 10; ++t) {
                const float vv = __half2float(Vs[k * KP + l + 32 * t]);
                accA[t] += fa * vv;
                accB[t] += fb * vv;
            }
        }
    }

    const float iA = 1.0f / sA, iB = 1.0f / sB;
    h16* Oa = O + ((long long)(b * Lq + q0 + qa)) * DD + h * HDIM;
#pragma unroll
    for (int t = 0; t < 10; ++t) {
        Oa[l + 32 * t]      = __float2half_rn(accA[t] * iA);
        Oa[DD + l + 32 * t] = __float2half_rn(accB[t] * iB);
    }
}

struct WSrc { const float* p[11]; };

__global__ void wsplit_all(WSrc ws, h16* __restrict__ hi) {
    const int mat = blockIdx.y;
    const long long o = (long long)mat * WMAT + (long long)blockIdx.x * 256 + threadIdx.x;
    hi[o] = __float2half_rn(ws.p[mat][(long long)blockIdx.x * 256 + threadIdx.x]);
}

__global__ void split_id(const float* __restrict__ x, h16* __restrict__ hi) {
    const long long o = (long long)blockIdx.x * 256 + threadIdx.x;
    hi[o] = __float2half_rn(x[o]);
}

__global__ void concat_split(const float* __restrict__ mem, const float* __restrict__ nm,
                             h16* __restrict__ hi) {
    const long long idx = (long long)blockIdx.x * 256 + threadIdx.x;
    const long long r = idx / (2 * DD);
    const int c = (int)(idx % (2 * DD));
    const float v = (c < DD) ? mem[r * DD + c] : nm[r * DD + c - DD];
    hi[idx] = __float2half_rn(v);
}

// ---- side streams (created pre-main) ---------------------------------------
struct SideStreams {
    cudaStream_t s1, s2;
    cudaEvent_t e0, eWs, eQG, eKVr, eOr, eVW, eMem;
    bool ok;
    SideStreams() {
        ok = cudaStreamCreateWithFlags(&s1, cudaStreamNonBlocking) == cudaSuccess &&
             cudaStreamCreateWithFlags(&s2, cudaStreamNonBlocking) == cudaSuccess &&
             cudaEventCreateWithFlags(&e0,  cudaEventDisableTiming) == cudaSuccess &&
             cudaEventCreateWithFlags(&eWs, cudaEventDisableTiming) == cudaSuccess &&
             cudaEventCreateWithFlags(&eQG, cudaEventDisableTiming) == cudaSuccess &&
             cudaEventCreateWithFlags(&eKVr,cudaEventDisableTiming) == cudaSuccess &&
             cudaEventCreateWithFlags(&eOr, cudaEventDisableTiming) == cudaSuccess &&
             cudaEventCreateWithFlags(&eVW, cudaEventDisableTiming) == cudaSuccess &&
             cudaEventCreateWithFlags(&eMem,cudaEventDisableTiming) == cudaSuccess;
    }
};
static SideStreams SS;

extern "C" void kernel_launch(void* const* d_in, const int* in_sizes, int n_in,
                              void* d_out, int out_size) {
    const float* hid      = (const float*)d_in[0];
    const float* init_mem = (const float*)d_in[1];
    const float* wq_r = (const float*)d_in[2];
    const float* wk_r = (const float*)d_in[3];
    const float* wv_r = (const float*)d_in[4];
    const float* wo_r = (const float*)d_in[5];
    const float* wg_r = (const float*)d_in[6];
    const float* bg_r = (const float*)d_in[7];
    const float* wqueries = (const float*)d_in[8];
    const float* wq_w = (const float*)d_in[9];
    const float* wk_w = (const float*)d_in[10];
    const float* wv_w = (const float*)d_in[11];
    const float* wo_w = (const float*)d_in[12];
    const float* wg_w = (const float*)d_in[13];
    const float* bg_w = (const float*)d_in[14];
    float* out = (float*)d_out;

    float *gate, *nm, *memA, *memB;
    h16 *whi, *hidhi, *chi, *ahi, *awhi, *cathi, *mAhi, *mBhi, *imhi, *wqhi;
    h16 *qrh, *kwh, *vwh, *krh, *vrh, *qwh;
    cudaGetSymbolAddress((void**)&gate, g_gate);  cudaGetSymbolAddress((void**)&nm, g_nm);
    cudaGetSymbolAddress((void**)&memA, g_memA);  cudaGetSymbolAddress((void**)&memB, g_memB);
    cudaGetSymbolAddress((void**)&whi, g_whi);
    cudaGetSymbolAddress((void**)&hidhi, g_hidhi);
    cudaGetSymbolAddress((void**)&chi, g_chi);
    cudaGetSymbolAddress((void**)&ahi, g_ahi);
    cudaGetSymbolAddress((void**)&awhi, g_awhi);
    cudaGetSymbolAddress((void**)&cathi, g_cathi);
    cudaGetSymbolAddress((void**)&mAhi, g_mAhi);
    cudaGetSymbolAddress((void**)&mBhi, g_mBhi);
    cudaGetSymbolAddress((void**)&imhi, g_imhi);
    cudaGetSymbolAddress((void**)&wqhi, g_wqhi);
    cudaGetSymbolAddress((void**)&qrh, g_qrh);  cudaGetSymbolAddress((void**)&kwh, g_kwh);
    cudaGetSymbolAddress((void**)&vwh, g_vwh);  cudaGetSymbolAddress((void**)&krh, g_krh);
    cudaGetSymbolAddress((void**)&vrh, g_vrh);  cudaGetSymbolAddress((void**)&qwh, g_qwh);

    constexpr int SMEM_BIG = 3 * (128 * 80 + 32 * 336);   // 62976
    constexpr int SMEM_SM  = 3 * (64  * 80 + 32 * 144);   // 29184
    constexpr int SMEM_ATT = 2 * KCH * KP * 2;            // 41216
    cudaFuncSetAttribute(mma_gemm<128,160,2,10,0,2>, cudaFuncAttributeMaxDynamicSharedMemorySize, SMEM_BIG);
    cudaFuncSetAttribute(mma_gemm<128,160,2,10,1,0>, cudaFuncAttributeMaxDynamicSharedMemorySize, SMEM_BIG);
    cudaFuncSetAttribute(mma_gemm<128,160,2,10,2,1>, cudaFuncAttributeMaxDynamicSharedMemorySize, SMEM_BIG);
    cudaFuncSetAttribute(mma_gemm<64,64,1,4,0,2>,    cudaFuncAttributeMaxDynamicSharedMemorySize, SMEM_SM);
    cudaFuncSetAttribute(mma_gemm<64,64,1,4,0,0>,    cudaFuncAttributeMaxDynamicSharedMemorySize, SMEM_SM);
    cudaFuncSetAttribute(mma_gemm<64,64,1,4,0,1>,    cudaFuncAttributeMaxDynamicSharedMemorySize, SMEM_SM);
    cudaFuncSetAttribute(mma_gemm<64,64,1,4,3,1>,    cudaFuncAttributeMaxDynamicSharedMemorySize, SMEM_SM);
    cudaFuncSetAttribute(attn16, cudaFuncAttributeMaxDynamicSharedMemorySize, SMEM_ATT);

    const float scale = 0.05590169943749474f;
    const size_t memBytesH = (size_t)MMEM * DD * sizeof(h16);
    dim3 gBig(DD / 160, MBIG / 128);   // 256 blocks
    dim3 gSm (DD / 64,  MSM / 64);     // 160 blocks
    dim3 gQw (DD / 64,  MMEM / 64);    // 80 blocks

    const bool ok = SS.ok;
    cudaStream_t t1 = ok ? SS.s1 : 0;
    cudaStream_t t2 = ok ? SS.s2 : 0;

    // ---- prologue ----
    if (ok) { cudaEventRecord(SS.e0, 0); cudaStreamWaitEvent(t1, SS.e0, 0);
              cudaStreamWaitEvent(t2, SS.e0, 0); }
    WSrc ws;
    ws.p[0] = wq_r; ws.p[1] = wk_r; ws.p[2] = wv_r; ws.p[3] = wo_r; ws.p[4] = wg_r;
    ws.p[5] = wq_w; ws.p[6] = wk_w; ws.p[7] = wv_w; ws.p[8] = wo_w;
    ws.p[9] = wg_w; ws.p[10] = wg_w + (long long)WMAT;
    wsplit_all<<<dim3(WMAT/256, 11), 256, 0, 0>>>(ws, whi);
    if (ok) cudaEventRecord(SS.eWs, 0);

    split_id<<<(BATCH*STOT*DD)/256, 256, 0, t1>>>(hid, hidhi);
    split_id<<<(MMEM*DD)/256, 256, 0, t2>>>(init_mem, imhi);
    split_id<<<(MMEM*DD)/256, 256, 0, t2>>>(wqueries, wqhi);

    if (ok) { cudaStreamWaitEvent(t1, SS.eWs, 0); cudaStreamWaitEvent(t2, SS.eWs, 0); }
    // t2: qw chain + kr/vr(0)
    mma_gemm<64,64,1,4,0,2><<<gQw, 256, SMEM_SM, t2>>>(wqhi,
        whi+OW_QW, nullptr, qwh, DD, DD, MMEM, 0, MMEM, 0,
        nullptr, nullptr, nullptr);
    cudaMemcpyAsync(qwh + (size_t)MMEM*DD, qwh, memBytesH, cudaMemcpyDeviceToDevice, t2);
    mma_gemm<64,64,1,4,0,2><<<gSm, 256, SMEM_SM, t2>>>(imhi,
        whi+OW_KR, nullptr, krh, DD, DD, MMEM, 0, MSM, 0,
        nullptr, nullptr, nullptr);
    mma_gemm<64,64,1,4,0,2><<<gSm, 256, SMEM_SM, t2>>>(imhi,
        whi+OW_VR, nullptr, vrh, DD, DD, MMEM, 0, MSM, 0,
        nullptr, nullptr, nullptr);
    if (ok) cudaEventRecord(SS.eKVr, t2);
    // t1: qr(0)/gate(0)
    mma_gemm<128,160,2,10,0,2><<<gBig, 256, SMEM_BIG, t1>>>(hidhi,
        whi+OW_QR, nullptr, qrh, DD, DD,
        SEGL, (long long)STOT, MBIG, 0, nullptr, nullptr, nullptr);
    mma_gemm<128,160,2,10,1,0><<<gBig, 256, SMEM_BIG, t1>>>(hidhi,
        whi+OW_GR, gate, nullptr, DD, DD,
        SEGL, (long long)STOT, MBIG, 0, bg_r, nullptr, nullptr);
    if (ok) cudaEventRecord(SS.eQG, t1);

    float* memf[2] = {memA, memB};
    h16*   memh[2] = {mAhi, mBhi};
    int cur = 0;

    for (int i = 0; i < NSEG; ++i) {
        const float* segp = hid + (long long)i * SEGL * DD;
        float* outp = out + (long long)i * SEGL * DD;
        const h16* nshi = hidhi + (long long)(i+1) * SEGL * DD;
        const bool NS = (i + 1 < NSEG);

        if (ok) { cudaStreamWaitEvent(0, SS.eQG, 0); cudaStreamWaitEvent(0, SS.eKVr, 0); }
        attn16<<<dim3(SEGL/16, NH, BATCH), 256, SMEM_ATT, 0>>>(qrh, krh, vrh, chi,
                                                               SEGL, MMEM, scale);
        mma_gemm<128,160,2,10,2,1><<<gBig, 256, SMEM_BIG, 0>>>(chi,
            whi+OW_OR, outp, ahi, DD, DD,
            MBIG, 0, SEGL, (long long)STOT, nullptr, segp, gate);
        if (ok) cudaEventRecord(SS.eOr, 0);

        if (NS) {
            if (ok) cudaStreamWaitEvent(t2, SS.eOr, 0);
            mma_gemm<128,160,2,10,0,2><<<gBig, 256, SMEM_BIG, t2>>>(nshi,
                whi+OW_QR, nullptr, qrh, DD, DD,
                SEGL, (long long)STOT, MBIG, 0, nullptr, nullptr, nullptr);
            mma_gemm<128,160,2,10,1,0><<<gBig, 256, SMEM_BIG, t2>>>(nshi,
                whi+OW_GR, gate, nullptr, DD, DD,
                SEGL, (long long)STOT, MBIG, 0, bg_r, nullptr, nullptr);
            if (ok) cudaEventRecord(SS.eQG, t2);
        }

        mma_gemm<128,160,2,10,0,2><<<gBig, 256, SMEM_BIG, 0>>>(ahi,
            whi+OW_KW, nullptr, kwh, DD, DD,
            MBIG, 0, MBIG, 0, nullptr, nullptr, nullptr);
        if (ok) cudaStreamWaitEvent(t1, SS.eOr, 0);
        mma_gemm<128,160,2,10,0,2><<<gBig, 256, SMEM_BIG, t1>>>(ahi,
            whi+OW_VW, nullptr, vwh, DD, DD,
            MBIG, 0, MBIG, 0, nullptr, nullptr, nullptr);
        if (ok) { cudaEventRecord(SS.eVW, t1); cudaStreamWaitEvent(0, SS.eVW, 0); }

        attn16<<<dim3(MMEM/16, NH, BATCH), 256, SMEM_ATT, 0>>>(qwh, kwh, vwh, awhi,
                                                               MMEM, SEGL, scale);

        if (i == 0) {
            mma_gemm<64,64,1,4,0,1><<<gSm, 256, SMEM_SM, 0>>>(awhi,
                whi+OW_OW, memf[0], mAhi, DD, DD,
                MSM, 0, MSM, 0, nullptr, nullptr, nullptr);
            cur = 0;
        } else {
            mma_gemm<64,64,1,4,0,0><<<gSm, 256, SMEM_SM, 0>>>(awhi,
                whi+OW_OW, nm, nullptr, DD, DD,
                MSM, 0, MSM, 0, nullptr, nullptr, nullptr);
            const int nxt = cur ^ 1;
            concat_split<<<(MSM*2*DD)/256, 256, 0, 0>>>(memf[cur], nm, cathi);
            mma_gemm<64,64,1,4,3,1><<<gSm, 256, SMEM_SM, 0>>>(cathi,
                whi+OW_GW, memf[nxt], memh[nxt], DD, 2*DD,
                MSM, 0, MSM, 0, bg_w, nm, memf[cur]);
            cur = nxt;
        }
        if (ok) cudaEventRecord(SS.eMem, 0);

        if (NS) {
            if (ok) cudaStreamWaitEvent(t1, SS.eMem, 0);
            mma_gemm<64,64,1,4,0,2><<<gSm, 256, SMEM_SM, t1>>>(memh[cur],
                whi+OW_KR, nullptr, krh, DD, DD,
                MSM, 0, MSM, 0, nullptr, nullptr, nullptr);
            mma_gemm<64,64,1,4,0,2><<<gSm, 256, SMEM_SM, t1>>>(memh[cur],
                whi+OW_VR, nullptr, vrh, DD, DD,
                MSM, 0, MSM, 0, nullptr, nullptr, nullptr);
            if (ok) cudaEventRecord(SS.eKVr, t1);
        }
    }
}

// round 17
// speedup vs baseline: 1.1870x; 1.1870x over previous
#include <cuda_runtime.h>
#include <cuda_fp16.h>
#include <math.h>
#include <stdint.h>
typedef __half h16;

#define DD    2560
#define HDIM  320
#define NH    8
#define SEGL  1024
#define STOT  4096
#define BATCH 2
#define MMEM  128
#define NSEG  4
#define MBIG  (BATCH*SEGL)
#define MSM   (BATCH*MMEM)
#define BKT   32

// fp32 scratch
__device__ float g_gate[MBIG*DD], g_nm[MSM*DD];
__device__ float g_memA[MSM*DD], g_memB[MSM*DD];
// fp16 scratch
#define WMAT (DD*DD)
__device__ __align__(16) h16 g_whi[11LL*WMAT];
__device__ __align__(16) h16 g_hidhi[BATCH*STOT*DD];
__device__ __align__(16) h16 g_qrh[MBIG*DD], g_kwh[MBIG*DD], g_vwh[MBIG*DD];
__device__ __align__(16) h16 g_krh[MSM*DD], g_vrh[MSM*DD], g_qwh[MSM*DD];
__device__ __align__(16) h16 g_chi[MBIG*DD];
__device__ __align__(16) h16 g_ahi[MBIG*DD];
__device__ __align__(16) h16 g_awhi[MSM*DD];
__device__ __align__(16) h16 g_cathi[MSM*2*DD];
__device__ __align__(16) h16 g_mAhi[MSM*DD];
__device__ __align__(16) h16 g_mBhi[MSM*DD];
__device__ __align__(16) h16 g_imhi[MMEM*DD];
__device__ __align__(16) h16 g_wqhi[MMEM*DD];

#define OW_QR (0LL*WMAT)
#define OW_KR (1LL*WMAT)
#define OW_VR (2LL*WMAT)
#define OW_OR (3LL*WMAT)
#define OW_GR (4LL*WMAT)
#define OW_QW (5LL*WMAT)
#define OW_KW (6LL*WMAT)
#define OW_VW (7LL*WMAT)
#define OW_OW (8LL*WMAT)
#define OW_GW (9LL*WMAT)

__device__ __forceinline__ void cp16(uint32_t s, const void* g) {
    asm volatile("cp.async.cg.shared.global [%0], [%1], 16;\n" :: "r"(s), "l"(g));
}
__device__ __forceinline__ void ldsm4(uint32_t& r0, uint32_t& r1, uint32_t& r2,
                                      uint32_t& r3, uint32_t a) {
    asm volatile("ldmatrix.sync.aligned.m8n8.x4.shared.b16 {%0,%1,%2,%3}, [%4];"
                 : "=r"(r0), "=r"(r1), "=r"(r2), "=r"(r3) : "r"(a));
}
__device__ __forceinline__ void ldsm4t(uint32_t& r0, uint32_t& r1, uint32_t& r2,
                                       uint32_t& r3, uint32_t a) {
    asm volatile("ldmatrix.sync.aligned.m8n8.x4.trans.shared.b16 {%0,%1,%2,%3}, [%4];"
                 : "=r"(r0), "=r"(r1), "=r"(r2), "=r"(r3) : "r"(a));
}
__device__ __forceinline__ void mma16816(float* c, const uint32_t* a, const uint32_t* b) {
    asm volatile("mma.sync.aligned.m16n8k16.row.col.f32.f16.f16.f32 "
                 "{%0,%1,%2,%3}, {%4,%5,%6,%7}, {%8,%9}, {%0,%1,%2,%3};"
                 : "+f"(c[0]), "+f"(c[1]), "+f"(c[2]), "+f"(c[3])
                 : "r"(a[0]), "r"(a[1]), "r"(a[2]), "r"(a[3]), "r"(b[0]), "r"(b[1]));
}
__device__ __forceinline__ float sig_(float x) { return 1.0f / (1.0f + __expf(-x)); }

// ---- single-pass fp16 HMMA GEMM, 2-stage cp.async pipeline ------------------
// OUT 0: C fp32 only.  OUT 1: C fp32 + Shi h16.  OUT 2: Shi h16 only.
template<int BM, int BN_, int MT, int NT_, int EPI, int OUT>
__global__ void __launch_bounds__(256, 2)
mma_gemm(const h16* __restrict__ Ah, const h16* __restrict__ Wh,
         float* __restrict__ C, h16* __restrict__ Shi,
         int N, int K, int a_cr, long long a_cs, int c_cr, long long c_cs,
         const float* __restrict__ aux0, const float* __restrict__ aux1,
         const float* __restrict__ aux2) {
    constexpr int WM = MT * 16, WN = NT_ * 8;
    constexpr int A_ROWB = BKT * 2 + 16;
    constexpr int B_ROWB = BN_ * 2 + 16;
    constexpr int A_TILE = BM * A_ROWB;
    constexpr int B_TILE = BKT * B_ROWB;
    constexpr int STAGE = A_TILE + B_TILE;
    constexpr int BCH = BN_ / 8;

    extern __shared__ char smem_raw[];
    const uint32_t sbase = (uint32_t)__cvta_generic_to_shared(smem_raw);

    const int tid = threadIdx.x;
    const int m0 = blockIdx.y * BM, n0 = blockIdx.x * BN_;
    const int warp = tid >> 5, lane = tid & 31;
    const int wid_m = warp >> 1, wid_n = warp & 1;
    const long long arow0 = (long long)(m0 / a_cr) * a_cs + (m0 % a_cr);

    float acc[MT][NT_][4];
#pragma unroll
    for (int i = 0; i < MT; ++i)
#pragma unroll
        for (int j = 0; j < NT_; ++j)
#pragma unroll
            for (int e = 0; e < 4; ++e) acc[i][j][e] = 0.0f;

    const int NKI = K / BKT;

    auto ldst = [&](int ks, int st) {
        const int k0 = ks * BKT;
        const uint32_t sb = sbase + st * STAGE;
#pragma unroll
        for (int t = 0; t < (BM * 4) / 256; ++t) {
            const int c = tid + t * 256;
            const int r = c >> 2, kc = (c & 3) * 8;
            const uint32_t off = r * A_ROWB + kc * 2;
            const long long gi = (arow0 + r) * (long long)K + k0 + kc;
            cp16(sb + off, Ah + gi);
        }
        for (int c = tid; c < 4 * BN_; c += 256) {
            const int r = c / BCH, nc = c % BCH;
            const uint32_t off = A_TILE + r * B_ROWB + nc * 16;
            const long long gi = (long long)(k0 + r) * N + n0 + nc * 8;
            cp16(sb + off, Wh + gi);
        }
        asm volatile("cp.async.commit_group;\n");
    };

    ldst(0, 0);
    ldst(1, 1);

    for (int ks = 0; ks < NKI; ++ks) {
        if (ks < NKI - 1) asm volatile("cp.async.wait_group 1;\n");
        else              asm volatile("cp.async.wait_group 0;\n");
        __syncthreads();
        const uint32_t sb = sbase + (ks & 1) * STAGE;

#pragma unroll
        for (int kk = 0; kk < BKT; kk += 16) {
            uint32_t ah[MT][4], b[NT_][2];
            const int arow = wid_m * WM + (lane & 15);
            const int acol = kk + (lane >> 4) * 8;
#pragma unroll
            for (int i = 0; i < MT; ++i) {
                const uint32_t ad = sb + (arow + i * 16) * A_ROWB + acol * 2;
                ldsm4(ah[i][0], ah[i][1], ah[i][2], ah[i][3], ad);
            }
            const int brow = kk + (lane & 15);
            const uint32_t bbase = sb + A_TILE + brow * B_ROWB;
#pragma unroll
            for (int j2 = 0; j2 < NT_ / 2; ++j2) {
                const int bcol = wid_n * WN + j2 * 16 + (lane >> 4) * 8;
                ldsm4t(b[2*j2][0], b[2*j2][1], b[2*j2+1][0], b[2*j2+1][1],
                       bbase + bcol * 2);
            }
#pragma unroll
            for (int i = 0; i < MT; ++i)
#pragma unroll
                for (int j = 0; j < NT_; ++j)
                    mma16816(acc[i][j], ah[i], b[j]);
        }
        __syncthreads();
        if (ks + 2 < NKI) ldst(ks + 2, ks & 1);
    }

    const int gid = lane >> 2, tig = lane & 3;
    const long long crow0 = (long long)(m0 / c_cr) * c_cs + (m0 % c_cr);

#pragma unroll
    for (int i = 0; i < MT; ++i) {
        const int r = wid_m * WM + i * 16 + gid;
#pragma unroll
        for (int j = 0; j < NT_; ++j) {
            const int col = n0 + wid_n * WN + j * 8 + 2 * tig;
#pragma unroll
            for (int half = 0; half < 2; ++half) {
                const int rr = r + half * 8;
                const long long ci = (crow0 + rr) * (long long)N + col;
                const long long li = (long long)(m0 + rr) * N + col;
                float2 v;
#pragma unroll
                for (int e = 0; e < 2; ++e) {
                    const float a = acc[i][j][2 * half + e];
                    float o;
                    if      (EPI == 0) o = a;
                    else if (EPI == 1) o = sig_(a + aux0[col + e]);
                    else if (EPI == 2) o = aux1[ci + e] + aux2[li + e] * a;
                    else { const float s = sig_(a + aux0[col + e]);
                           o = s * aux1[li + e] + (1.0f - s) * aux2[li + e]; }
                    (&v.x)[e] = o;
                }
                if (OUT <= 1) *reinterpret_cast<float2*>(C + ci) = v;
                if (OUT >= 1)
                    *reinterpret_cast<__half2*>(Shi + li) =
                        __half2(__float2half_rn(v.x), __float2half_rn(v.y));
            }
        }
    }
}

// ---- flash attention (round-13 proven structure), h16 in / h16 out ---------
// 16 queries/block, warp w owns queries 2w, 2w+1. K/V converted to fp32 smem.
__global__ void __launch_bounds__(256)
attn16(const h16* __restrict__ Q, const h16* __restrict__ Kp,
       const h16* __restrict__ V, h16* __restrict__ O,
       int Lq, int Lk, float scale) {
    __shared__ float Ks[16][HDIM], Vs[16][HDIM];
    const int h = blockIdx.y, b = blockIdx.z, q0 = blockIdx.x * 16;
    const int tid = threadIdx.x, w = tid >> 5, l = tid & 31;
    const int qa = q0 + 2 * w;

    float qA[10], qB[10];
    const h16* Qb = Q + ((long long)(b * Lq + qa)) * DD + h * HDIM;
#pragma unroll
    for (int t = 0; t < 10; ++t) {
        qA[t] = __half2float(Qb[l + 32 * t]);
        qB[t] = __half2float(Qb[DD + l + 32 * t]);
    }

    float mrun = -1e30f, sA = 0.0f, sB = 0.0f, accA[10], accB[10];
#pragma unroll
    for (int t = 0; t < 10; ++t) { accA[t] = 0.0f; accB[t] = 0.0f; }

    for (int c = 0; c < Lk / 16; ++c) {
        const long long k0 = (long long)(b * Lk + c * 16) * DD + h * HDIM;
#pragma unroll
        for (int t = 0; t < 5; ++t) {
            const int idx = tid + t * 256;
            const int row = idx / 80, c4 = idx % 80;
            const __half2* kp2 = reinterpret_cast<const __half2*>(
                Kp + k0 + (long long)row * DD + c4 * 4);
            const __half2* vp2 = reinterpret_cast<const __half2*>(
                V + k0 + (long long)row * DD + c4 * 4);
            const float2 ka = __half22float2(kp2[0]), kb = __half22float2(kp2[1]);
            const float2 va = __half22float2(vp2[0]), vb = __half22float2(vp2[1]);
            float4 kf; kf.x = ka.x; kf.y = ka.y; kf.z = kb.x; kf.w = kb.y;
            float4 vf; vf.x = va.x; vf.y = va.y; vf.z = vb.x; vf.w = vb.y;
            *reinterpret_cast<float4*>(&Ks[row][c4 * 4]) = kf;
            *reinterpret_cast<float4*>(&Vs[row][c4 * 4]) = vf;
        }
        __syncthreads();
        float scA[16], scB[16], cmax = -1e30f;
#pragma unroll
        for (int k = 0; k < 16; ++k) {
            float da = 0.0f, db = 0.0f;
#pragma unroll
            for (int t = 0; t < 10; ++t) {
                const float kv = Ks[k][l + 32 * t];
                da += qA[t] * kv; db += qB[t] * kv;
            }
#pragma unroll
            for (int o = 16; o > 0; o >>= 1) {
                da += __shfl_xor_sync(0xFFFFFFFF, da, o);
                db += __shfl_xor_sync(0xFFFFFFFF, db, o);
            }
            scA[k] = da * scale; scB[k] = db * scale;
            cmax = fmaxf(cmax, fmaxf(scA[k], scB[k]));
        }
        const float mn = fmaxf(mrun, cmax);
        const float cr = __expf(mrun - mn);
        sA *= cr; sB *= cr;
#pragma unroll
        for (int t = 0; t < 10; ++t) { accA[t] *= cr; accB[t] *= cr; }
        mrun = mn;
#pragma unroll
        for (int k = 0; k < 16; ++k) {
            const float pa = __expf(scA[k] - mn), pb = __expf(scB[k] - mn);
            sA += pa; sB += pb;
#pragma unroll
            for (int t = 0; t < 10; ++t) {
                const float vv = Vs[k][l + 32 * t];
                accA[t] += pa * vv; accB[t] += pb * vv;
            }
        }
        __syncthreads();
    }
    const float iA = 1.0f / sA, iB = 1.0f / sB;
    h16* Oh = O + ((long long)(b * Lq + qa)) * DD + h * HDIM;
#pragma unroll
    for (int t = 0; t < 10; ++t) {
        Oh[l + 32 * t]      = __float2half_rn(accA[t] * iA);
        Oh[DD + l + 32 * t] = __float2half_rn(accB[t] * iB);
    }
}

struct WSrc { const float* p[11]; };

__global__ void wsplit_all(WSrc ws, h16* __restrict__ hi) {
    const int mat = blockIdx.y;
    const long long o = (long long)mat * WMAT + (long long)blockIdx.x * 256 + threadIdx.x;
    hi[o] = __float2half_rn(ws.p[mat][(long long)blockIdx.x * 256 + threadIdx.x]);
}

__global__ void split_id(const float* __restrict__ x, h16* __restrict__ hi) {
    const long long o = (long long)blockIdx.x * 256 + threadIdx.x;
    hi[o] = __float2half_rn(x[o]);
}

__global__ void concat_split(const float* __restrict__ mem, const float* __restrict__ nm,
                             h16* __restrict__ hi) {
    const long long idx = (long long)blockIdx.x * 256 + threadIdx.x;
    const long long r = idx / (2 * DD);
    const int c = (int)(idx % (2 * DD));
    const float v = (c < DD) ? mem[r * DD + c] : nm[r * DD + c - DD];
    hi[idx] = __float2half_rn(v);
}

// ---- side streams (created pre-main) ---------------------------------------
struct SideStreams {
    cudaStream_t s1, s2;
    cudaEvent_t e0, eWs, eQG, eKVr, eOr, eVW, eMem;
    bool ok;
    SideStreams() {
        ok = cudaStreamCreateWithFlags(&s1, cudaStreamNonBlocking) == cudaSuccess &&
             cudaStreamCreateWithFlags(&s2, cudaStreamNonBlocking) == cudaSuccess &&
             cudaEventCreateWithFlags(&e0,  cudaEventDisableTiming) == cudaSuccess &&
             cudaEventCreateWithFlags(&eWs, cudaEventDisableTiming) == cudaSuccess &&
             cudaEventCreateWithFlags(&eQG, cudaEventDisableTiming) == cudaSuccess &&
             cudaEventCreateWithFlags(&eKVr,cudaEventDisableTiming) == cudaSuccess &&
             cudaEventCreateWithFlags(&eOr, cudaEventDisableTiming) == cudaSuccess &&
             cudaEventCreateWithFlags(&eVW, cudaEventDisableTiming) == cudaSuccess &&
             cudaEventCreateWithFlags(&eMem,cudaEventDisableTiming) == cudaSuccess;
    }
};
static SideStreams SS;

extern "C" void kernel_launch(void* const* d_in, const int* in_sizes, int n_in,
                              void* d_out, int out_size) {
    const float* hid      = (const float*)d_in[0];
    const float* init_mem = (const float*)d_in[1];
    const float* wq_r = (const float*)d_in[2];
    const float* wk_r = (const float*)d_in[3];
    const float* wv_r = (const float*)d_in[4];
    const float* wo_r = (const float*)d_in[5];
    const float* wg_r = (const float*)d_in[6];
    const float* bg_r = (const float*)d_in[7];
    const float* wqueries = (const float*)d_in[8];
    const float* wq_w = (const float*)d_in[9];
    const float* wk_w = (const float*)d_in[10];
    const float* wv_w = (const float*)d_in[11];
    const float* wo_w = (const float*)d_in[12];
    const float* wg_w = (const float*)d_in[13];
    const float* bg_w = (const float*)d_in[14];
    float* out = (float*)d_out;

    float *gate, *nm, *memA, *memB;
    h16 *whi, *hidhi, *chi, *ahi, *awhi, *cathi, *mAhi, *mBhi, *imhi, *wqhi;
    h16 *qrh, *kwh, *vwh, *krh, *vrh, *qwh;
    cudaGetSymbolAddress((void**)&gate, g_gate);  cudaGetSymbolAddress((void**)&nm, g_nm);
    cudaGetSymbolAddress((void**)&memA, g_memA);  cudaGetSymbolAddress((void**)&memB, g_memB);
    cudaGetSymbolAddress((void**)&whi, g_whi);
    cudaGetSymbolAddress((void**)&hidhi, g_hidhi);
    cudaGetSymbolAddress((void**)&chi, g_chi);
    cudaGetSymbolAddress((void**)&ahi, g_ahi);
    cudaGetSymbolAddress((void**)&awhi, g_awhi);
    cudaGetSymbolAddress((void**)&cathi, g_cathi);
    cudaGetSymbolAddress((void**)&mAhi, g_mAhi);
    cudaGetSymbolAddress((void**)&mBhi, g_mBhi);
    cudaGetSymbolAddress((void**)&imhi, g_imhi);
    cudaGetSymbolAddress((void**)&wqhi, g_wqhi);
    cudaGetSymbolAddress((void**)&qrh, g_qrh);  cudaGetSymbolAddress((void**)&kwh, g_kwh);
    cudaGetSymbolAddress((void**)&vwh, g_vwh);  cudaGetSymbolAddress((void**)&krh, g_krh);
    cudaGetSymbolAddress((void**)&vrh, g_vrh);  cudaGetSymbolAddress((void**)&qwh, g_qwh);

    constexpr int SMEM_BIG = 2 * (128 * 80 + 32 * 336);   // 41984
    constexpr int SMEM_SM  = 2 * (64  * 80 + 32 * 144);   // 19456
    cudaFuncSetAttribute(mma_gemm<128,160,2,10,0,2>, cudaFuncAttributeMaxDynamicSharedMemorySize, SMEM_BIG);
    cudaFuncSetAttribute(mma_gemm<128,160,2,10,1,0>, cudaFuncAttributeMaxDynamicSharedMemorySize, SMEM_BIG);
    cudaFuncSetAttribute(mma_gemm<128,160,2,10,2,1>, cudaFuncAttributeMaxDynamicSharedMemorySize, SMEM_BIG);
    cudaFuncSetAttribute(mma_gemm<64,64,1,4,0,2>,    cudaFuncAttributeMaxDynamicSharedMemorySize, SMEM_SM);
    cudaFuncSetAttribute(mma_gemm<64,64,1,4,0,0>,    cudaFuncAttributeMaxDynamicSharedMemorySize, SMEM_SM);
    cudaFuncSetAttribute(mma_gemm<64,64,1,4,0,1>,    cudaFuncAttributeMaxDynamicSharedMemorySize, SMEM_SM);
    cudaFuncSetAttribute(mma_gemm<64,64,1,4,3,1>,    cudaFuncAttributeMaxDynamicSharedMemorySize, SMEM_SM);

    const float scale = 0.05590169943749474f;
    const size_t memBytesH = (size_t)MMEM * DD * sizeof(h16);
    dim3 gBig(DD / 160, MBIG / 128);   // 256 blocks
    dim3 gSm (DD / 64,  MSM / 64);     // 160 blocks
    dim3 gQw (DD / 64,  MMEM / 64);    // 80 blocks

    const bool ok = SS.ok;
    cudaStream_t t1 = ok ? SS.s1 : 0;
    cudaStream_t t2 = ok ? SS.s2 : 0;

    // ---- prologue ----
    if (ok) { cudaEventRecord(SS.e0, 0); cudaStreamWaitEvent(t1, SS.e0, 0);
              cudaStreamWaitEvent(t2, SS.e0, 0); }
    WSrc ws;
    ws.p[0] = wq_r; ws.p[1] = wk_r; ws.p[2] = wv_r; ws.p[3] = wo_r; ws.p[4] = wg_r;
    ws.p[5] = wq_w; ws.p[6] = wk_w; ws.p[7] = wv_w; ws.p[8] = wo_w;
    ws.p[9] = wg_w; ws.p[10] = wg_w + (long long)WMAT;
    wsplit_all<<<dim3(WMAT/256, 11), 256, 0, 0>>>(ws, whi);
    if (ok) cudaEventRecord(SS.eWs, 0);

    split_id<<<(BATCH*STOT*DD)/256, 256, 0, t1>>>(hid, hidhi);
    split_id<<<(MMEM*DD)/256, 256, 0, t2>>>(init_mem, imhi);
    split_id<<<(MMEM*DD)/256, 256, 0, t2>>>(wqueries, wqhi);

    if (ok) { cudaStreamWaitEvent(t1, SS.eWs, 0); cudaStreamWaitEvent(t2, SS.eWs, 0); }
    // t2: qw chain + kr/vr(0)
    mma_gemm<64,64,1,4,0,2><<<gQw, 256, SMEM_SM, t2>>>(wqhi,
        whi+OW_QW, nullptr, qwh, DD, DD, MMEM, 0, MMEM, 0,
        nullptr, nullptr, nullptr);
    cudaMemcpyAsync(qwh + (size_t)MMEM*DD, qwh, memBytesH, cudaMemcpyDeviceToDevice, t2);
    mma_gemm<64,64,1,4,0,2><<<gSm, 256, SMEM_SM, t2>>>(imhi,
        whi+OW_KR, nullptr, krh, DD, DD, MMEM, 0, MSM, 0,
        nullptr, nullptr, nullptr);
    mma_gemm<64,64,1,4,0,2><<<gSm, 256, SMEM_SM, t2>>>(imhi,
        whi+OW_VR, nullptr, vrh, DD, DD, MMEM, 0, MSM, 0,
        nullptr, nullptr, nullptr);
    if (ok) cudaEventRecord(SS.eKVr, t2);
    // t1: qr(0)/gate(0)
    mma_gemm<128,160,2,10,0,2><<<gBig, 256, SMEM_BIG, t1>>>(hidhi,
        whi+OW_QR, nullptr, qrh, DD, DD,
        SEGL, (long long)STOT, MBIG, 0, nullptr, nullptr, nullptr);
    mma_gemm<128,160,2,10,1,0><<<gBig, 256, SMEM_BIG, t1>>>(hidhi,
        whi+OW_GR, gate, nullptr, DD, DD,
        SEGL, (long long)STOT, MBIG, 0, bg_r, nullptr, nullptr);
    if (ok) cudaEventRecord(SS.eQG, t1);

    float* memf[2] = {memA, memB};
    h16*   memh[2] = {mAhi, mBhi};
    int cur = 0;

    for (int i = 0; i < NSEG; ++i) {
        const float* segp = hid + (long long)i * SEGL * DD;
        float* outp = out + (long long)i * SEGL * DD;
        const h16* nshi = hidhi + (long long)(i+1) * SEGL * DD;
        const bool NS = (i + 1 < NSEG);

        if (ok) { cudaStreamWaitEvent(0, SS.eQG, 0); cudaStreamWaitEvent(0, SS.eKVr, 0); }
        attn16<<<dim3(SEGL/16, NH, BATCH), 256, 0, 0>>>(qrh, krh, vrh, chi,
                                                        SEGL, MMEM, scale);
        mma_gemm<128,160,2,10,2,1><<<gBig, 256, SMEM_BIG, 0>>>(chi,
            whi+OW_OR, outp, ahi, DD, DD,
            MBIG, 0, SEGL, (long long)STOT, nullptr, segp, gate);
        if (ok) cudaEventRecord(SS.eOr, 0);

        if (NS) {
            if (ok) cudaStreamWaitEvent(t2, SS.eOr, 0);
            mma_gemm<128,160,2,10,0,2><<<gBig, 256, SMEM_BIG, t2>>>(nshi,
                whi+OW_QR, nullptr, qrh, DD, DD,
                SEGL, (long long)STOT, MBIG, 0, nullptr, nullptr, nullptr);
            mma_gemm<128,160,2,10,1,0><<<gBig, 256, SMEM_BIG, t2>>>(nshi,
                whi+OW_GR, gate, nullptr, DD, DD,
                SEGL, (long long)STOT, MBIG, 0, bg_r, nullptr, nullptr);
            if (ok) cudaEventRecord(SS.eQG, t2);
        }

        mma_gemm<128,160,2,10,0,2><<<gBig, 256, SMEM_BIG, 0>>>(ahi,
            whi+OW_KW, nullptr, kwh, DD, DD,
            MBIG, 0, MBIG, 0, nullptr, nullptr, nullptr);
        if (ok) cudaStreamWaitEvent(t1, SS.eOr, 0);
        mma_gemm<128,160,2,10,0,2><<<gBig, 256, SMEM_BIG, t1>>>(ahi,
            whi+OW_VW, nullptr, vwh, DD, DD,
            MBIG, 0, MBIG, 0, nullptr, nullptr, nullptr);
        if (ok) { cudaEventRecord(SS.eVW, t1); cudaStreamWaitEvent(0, SS.eVW, 0); }

        attn16<<<dim3(MMEM/16, NH, BATCH), 256, 0, 0>>>(qwh, kwh, vwh, awhi,
                                                        MMEM, SEGL, scale);

        if (i == 0) {
            mma_gemm<64,64,1,4,0,1><<<gSm, 256, SMEM_SM, 0>>>(awhi,
                whi+OW_OW, memf[0], mAhi, DD, DD,
                MSM, 0, MSM, 0, nullptr, nullptr, nullptr);
            cur = 0;
        } else {
            mma_gemm<64,64,1,4,0,0><<<gSm, 256, SMEM_SM, 0>>>(awhi,
                whi+OW_OW, nm, nullptr, DD, DD,
                MSM, 0, MSM, 0, nullptr, nullptr, nullptr);
            const int nxt = cur ^ 1;
            concat_split<<<(MSM*2*DD)/256, 256, 0, 0>>>(memf[cur], nm, cathi);
            mma_gemm<64,64,1,4,3,1><<<gSm, 256, SMEM_SM, 0>>>(cathi,
                whi+OW_GW, memf[nxt], memh[nxt], DD, 2*DD,
                MSM, 0, MSM, 0, bg_w, nm, memf[cur]);
            cur = nxt;
        }
        if (ok) cudaEventRecord(SS.eMem, 0);

        if (NS) {
            if (ok) cudaStreamWaitEvent(t1, SS.eMem, 0);
            mma_gemm<64,64,1,4,0,2><<<gSm, 256, SMEM_SM, t1>>>(memh[cur],
                whi+OW_KR, nullptr, krh, DD, DD,
                MSM, 0, MSM, 0, nullptr, nullptr, nullptr);
            mma_gemm<64,64,1,4,0,2><<<gSm, 256, SMEM_SM, t1>>>(memh[cur],
                whi+OW_VR, nullptr, vrh, DD, DD,
                MSM, 0, MSM, 0, nullptr, nullptr, nullptr);
            if (ok) cudaEventRecord(SS.eKVr, t1);
        }
    }
}